// round 5
// baseline (speedup 1.0000x reference)
#include <cuda_runtime.h>

#define NB 16
#define NS 4
#define NK 11
#define NBS (NB * NS)   // 64 CTAs
#define NTHR 512

__global__ void __launch_bounds__(NTHR, 1)
keypoint_fused_kernel(const float* __restrict__ cp,     // (16,4,22,128,128)
                      const float* __restrict__ heat,   // (16,11,128,128)
                      const float* __restrict__ lab,    // (16,11,11)
                      float* __restrict__ out)          // 128 floats
{
    const int bs = blockIdx.x;           // 0..63  (b*4+s)
    const int b  = bs >> 2;
    const int t  = threadIdx.x;          // 0..511

    // hm maps for this (b,s): channels 0..10 of 22
    const float4* __restrict__ hbase =
        (const float4*)(cp + ((size_t)(bs * 22) << 14));
    const float4* __restrict__ gbase =
        (const float4*)(heat + ((size_t)(b * NK) << 14));

    float sums[NK];
    float mxv[NK];
    int   miv[NK];

    #pragma unroll
    for (int k = 0; k < NK; k++) {
        const float4* __restrict__ hp = hbase + ((size_t)k << 12); // 4096 f4/map
        const float4* __restrict__ gp = gbase + ((size_t)k << 12);

        float s  = 0.0f;
        float mx = -__int_as_float(0x7f800000); // -inf
        int   mi = 0;

        #pragma unroll
        for (int j = 0; j < 8; j++) {
            const int v = t + j * NTHR;          // [0,4096)
            const float4 h = hp[v];
            const float4 g = gp[v];
            float d0 = h.x - g.x, d1 = h.y - g.y;
            float d2 = h.z - g.z, d3 = h.w - g.w;
            s = fmaf(d0, d0, s);
            s = fmaf(d1, d1, s);
            s = fmaf(d2, d2, s);
            s = fmaf(d3, d3, s);
            const int base = v << 2;
            // ascending global index within thread -> strict > = first occurrence
            if (h.x > mx) { mx = h.x; mi = base; }
            if (h.y > mx) { mx = h.y; mi = base + 1; }
            if (h.z > mx) { mx = h.z; mi = base + 2; }
            if (h.w > mx) { mx = h.w; mi = base + 3; }
        }
        sums[k] = s; mxv[k] = mx; miv[k] = mi;
    }

    // Warp-level reduce for every k (min-index tiebreak on global index)
    #pragma unroll
    for (int k = 0; k < NK; k++) {
        float s  = sums[k];
        float mx = mxv[k];
        int   mi = miv[k];
        #pragma unroll
        for (int off = 16; off > 0; off >>= 1) {
            float os  = __shfl_down_sync(0xffffffffu, s,  off);
            float omx = __shfl_down_sync(0xffffffffu, mx, off);
            int   omi = __shfl_down_sync(0xffffffffu, mi, off);
            s += os;
            if (omx > mx || (omx == mx && omi < mi)) { mx = omx; mi = omi; }
        }
        sums[k] = s; mxv[k] = mx; miv[k] = mi;
    }

    __shared__ float ssum[16][NK];
    __shared__ float smx [16][NK];
    __shared__ int   smi [16][NK];
    __shared__ float s_heat[NK];
    __shared__ float s_lab [NK];

    const int w = t >> 5, l = t & 31;
    if (l == 0) {
        #pragma unroll
        for (int k = 0; k < NK; k++) {
            ssum[w][k] = sums[k];
            smx [w][k] = mxv[k];
            smi [w][k] = miv[k];
        }
    }
    __syncthreads();

    if (t < NK) {
        const int k = t;
        float s  = ssum[0][k];
        float mx = smx [0][k];
        int   mi = smi [0][k];
        #pragma unroll
        for (int w2 = 1; w2 < 16; w2++) {
            s += ssum[w2][k];
            const float omx = smx[w2][k];
            const int   omi = smi[w2][k];
            if (omx > mx || (omx == mx && omi < mi)) { mx = omx; mi = omi; }
        }

        // ---- label-loss term for this (b,s,k) ----
        const float* __restrict__ lp =
            cp + ((size_t)(bs * 22 + NK + k) << 14);   // lb map, first 9 used
        const float* __restrict__ lb = lab + (size_t)(b * NK + k) * 11;

        const float gx = lb[9];
        const float gy = lb[10];
        const bool valid = (gx > 0.0f) && (gy > 0.0f) &&
                           (gx < 128.0f) && (gy < 128.0f);

        const float xf = (float)(mi >> 7);    // index // 128
        const float yf = (float)(mi & 127);   // index % 128

        const float dx = gx + lb[7] - xf - lp[7];
        const float dy = gy + lb[8] - yf - lp[8];
        const float xy_loss = dx * dx + dy * dy;

        const float c = 1.0f - mx;
        const float conf_loss = c * c;

        float cls = 0.0f;
        #pragma unroll
        for (int j = 0; j < 7; j++) {
            const float d = lp[j] - lb[j];
            cls = fmaf(d, d, cls);
        }

        s_heat[k] = s;
        s_lab [k] = valid ? (cls + xy_loss + conf_loss) : 0.0f;
    }
    __syncthreads();

    if (t == 0) {
        float hsum = 0.0f, lsum = 0.0f;
        #pragma unroll
        for (int k = 0; k < NK; k++) {
            hsum += s_heat[k];
            lsum += s_lab [k];
        }
        out[bs]      = hsum;   // heat_loss (16,4)
        out[64 + bs] = lsum;   // label_loss (16,4)
    }
}

extern "C" void kernel_launch(void* const* d_in, const int* in_sizes, int n_in,
                              void* d_out, int out_size)
{
    const float* cp   = (const float*)d_in[0]; // combined_preds
    const float* heat = (const float*)d_in[1]; // heatmaps
    const float* lab  = (const float*)d_in[2]; // labels
    float* out = (float*)d_out;

    keypoint_fused_kernel<<<NBS, NTHR>>>(cp, heat, lab, out);
}

// round 6
// speedup vs baseline: 1.6156x; 1.6156x over previous
#include <cuda_runtime.h>

#define NB 16
#define NS 4
#define NK 11
#define NBS (NB * NS)         // 64
#define NBSK (NB * NS * NK)   // 704

// Scratch: per-(b,s,k) partials + per-(b,s) arrival counters. Static device
// globals (no allocation). Counters zero at load; finisher resets them each
// launch so graph replays are deterministic.
__device__ float    g_part[2 * NBSK];
__device__ unsigned g_cnt[NBS];

__device__ __forceinline__ unsigned atom_add_acq_rel_gpu(unsigned* p, unsigned v)
{
    unsigned old;
    asm volatile("atom.acq_rel.gpu.global.add.u32 %0, [%1], %2;"
                 : "=r"(old) : "l"(p), "r"(v) : "memory");
    return old;
}

__global__ void __launch_bounds__(256, 4)
keypoint_main_kernel(const float* __restrict__ cp,     // (16,4,22,128,128)
                     const float* __restrict__ heat,   // (16,11,128,128)
                     const float* __restrict__ lab,    // (16,11,11)
                     float* __restrict__ out)          // 128 floats
{
    const int bsk = blockIdx.x;          // 0..703
    const int k   = bsk % NK;
    const int bs  = bsk / NK;            // b*4+s
    const int b   = bs / NS;

    const float4* __restrict__ hptr =
        (const float4*)(cp + ((size_t)(bs * 22 + k) << 14));
    const float4* __restrict__ gptr =
        (const float4*)(heat + ((size_t)(b * NK + k) << 14));

    const int t = threadIdx.x;           // 0..255

    float sum = 0.0f;
    float mx  = -__int_as_float(0x7f800000); // -inf
    int   mi  = 0;

    #pragma unroll
    for (int j = 0; j < 16; j++) {
        const int v = t + j * 256;       // float4 index in [0,4096)
        const float4 h = hptr[v];
        const float4 g = gptr[v];
        float d0 = h.x - g.x, d1 = h.y - g.y, d2 = h.z - g.z, d3 = h.w - g.w;
        sum = fmaf(d0, d0, sum);
        sum = fmaf(d1, d1, sum);
        sum = fmaf(d2, d2, sum);
        sum = fmaf(d3, d3, sum);
        const int base = v << 2;
        // ascending index within thread -> strict > keeps first occurrence
        if (h.x > mx) { mx = h.x; mi = base; }
        if (h.y > mx) { mx = h.y; mi = base + 1; }
        if (h.z > mx) { mx = h.z; mi = base + 2; }
        if (h.w > mx) { mx = h.w; mi = base + 3; }
    }

    // Warp reduce (sum, argmax with lowest-index tiebreak)
    #pragma unroll
    for (int off = 16; off > 0; off >>= 1) {
        float osum = __shfl_down_sync(0xffffffffu, sum, off);
        float omx  = __shfl_down_sync(0xffffffffu, mx,  off);
        int   omi  = __shfl_down_sync(0xffffffffu, mi,  off);
        sum += osum;
        if (omx > mx || (omx == mx && omi < mi)) { mx = omx; mi = omi; }
    }

    __shared__ float ssum[8];
    __shared__ float smx[8];
    __shared__ int   smi[8];
    const int w = t >> 5, l = t & 31;
    if (l == 0) { ssum[w] = sum; smx[w] = mx; smi[w] = mi; }
    __syncthreads();

    if (t == 0) {
        #pragma unroll
        for (int w2 = 1; w2 < 8; w2++) {
            sum += ssum[w2];
            if (smx[w2] > mx || (smx[w2] == mx && smi[w2] < mi)) {
                mx = smx[w2]; mi = smi[w2];
            }
        }

        // ---- label-loss term for this (b,s,k) ----
        const float* __restrict__ lp =
            cp + ((size_t)(bs * 22 + NK + k) << 14);     // lb map, first 9 used
        const float* __restrict__ lb = lab + (size_t)(b * NK + k) * 11;

        const float gx = lb[9];
        const float gy = lb[10];
        const bool valid = (gx > 0.0f) && (gy > 0.0f) &&
                           (gx < 128.0f) && (gy < 128.0f);

        const float xf = (float)(mi >> 7);    // index // 128
        const float yf = (float)(mi & 127);   // index % 128

        const float dx = gx + lb[7] - xf - lp[7];
        const float dy = gy + lb[8] - yf - lp[8];
        const float xy_loss = dx * dx + dy * dy;

        const float c = 1.0f - mx;
        const float conf_loss = c * c;

        float cls = 0.0f;
        #pragma unroll
        for (int j = 0; j < 7; j++) {
            const float d = lp[j] - lb[j];
            cls = fmaf(d, d, cls);
        }

        // L1-bypass stores: visible at L2 for any finisher CTA on any SM.
        __stcg(&g_part[bsk], sum);
        __stcg(&g_part[NBSK + bsk],
               valid ? (cls + xy_loss + conf_loss) : 0.0f);

        // acq_rel atomic: release orders the .cg stores above, acquire orders
        // the .cg loads below. No MEMBAR / CCTL.IVALL emitted.
        const unsigned prev = atom_add_acq_rel_gpu(&g_cnt[bs], 1u);
        if (prev == NK - 1) {
            g_cnt[bs] = 0;               // reset for next graph replay
            float hsum = 0.0f, lsum = 0.0f;
            #pragma unroll
            for (int kk = 0; kk < NK; kk++) {
                hsum += __ldcg(&g_part[bs * NK + kk]);
                lsum += __ldcg(&g_part[NBSK + bs * NK + kk]);
            }
            out[bs]      = hsum;         // heat_loss (16,4)
            out[64 + bs] = lsum;         // label_loss (16,4)
        }
    }
}

extern "C" void kernel_launch(void* const* d_in, const int* in_sizes, int n_in,
                              void* d_out, int out_size)
{
    const float* cp   = (const float*)d_in[0]; // combined_preds
    const float* heat = (const float*)d_in[1]; // heatmaps
    const float* lab  = (const float*)d_in[2]; // labels
    float* out = (float*)d_out;

    keypoint_main_kernel<<<NBSK, 256>>>(cp, heat, lab, out);
}

// round 7
// speedup vs baseline: 1.8175x; 1.1250x over previous
#include <cuda_runtime.h>

#define NB 16
#define NS 4
#define NK 11
#define NBS (NB * NS)         // 64
#define NBSK (NB * NS * NK)   // 704

// Scratch: per-(b,s,k) partials + per-(b,s) arrival counters. Static device
// globals (no allocation). Counters zero at load; finisher resets them each
// launch so graph replays are deterministic.
__device__ float    g_part[2 * NBSK];
__device__ unsigned g_cnt[NBS];

// RELEASE-only atomic: orders this thread's prior stores (our .cg partials)
// before the increment becomes visible. No acquire half -> no CCTL.IVALL
// (full L1D invalidate) is emitted, which was costing ~6us across 704 CTAs.
__device__ __forceinline__ unsigned atom_add_release_gpu(unsigned* p, unsigned v)
{
    unsigned old;
    asm volatile("atom.release.gpu.global.add.u32 %0, [%1], %2;"
                 : "=r"(old) : "l"(p), "r"(v) : "memory");
    return old;
}

__global__ void __launch_bounds__(256, 4)
keypoint_main_kernel(const float* __restrict__ cp,     // (16,4,22,128,128)
                     const float* __restrict__ heat,   // (16,11,128,128)
                     const float* __restrict__ lab,    // (16,11,11)
                     float* __restrict__ out)          // 128 floats
{
    const int bsk = blockIdx.x;          // 0..703
    const int k   = bsk % NK;
    const int bs  = bsk / NK;            // b*4+s
    const int b   = bs / NS;

    const float4* __restrict__ hptr =
        (const float4*)(cp + ((size_t)(bs * 22 + k) << 14));
    const float4* __restrict__ gptr =
        (const float4*)(heat + ((size_t)(b * NK + k) << 14));

    const int t = threadIdx.x;           // 0..255

    float sum = 0.0f;
    float mx  = -__int_as_float(0x7f800000); // -inf
    int   mi  = 0;

    #pragma unroll
    for (int j = 0; j < 16; j++) {
        const int v = t + j * 256;       // float4 index in [0,4096)
        const float4 h = hptr[v];
        const float4 g = gptr[v];
        float d0 = h.x - g.x, d1 = h.y - g.y, d2 = h.z - g.z, d3 = h.w - g.w;
        sum = fmaf(d0, d0, sum);
        sum = fmaf(d1, d1, sum);
        sum = fmaf(d2, d2, sum);
        sum = fmaf(d3, d3, sum);
        const int base = v << 2;
        // ascending index within thread -> strict > keeps first occurrence
        if (h.x > mx) { mx = h.x; mi = base; }
        if (h.y > mx) { mx = h.y; mi = base + 1; }
        if (h.z > mx) { mx = h.z; mi = base + 2; }
        if (h.w > mx) { mx = h.w; mi = base + 3; }
    }

    // Warp reduce (sum, argmax with lowest-index tiebreak)
    #pragma unroll
    for (int off = 16; off > 0; off >>= 1) {
        float osum = __shfl_down_sync(0xffffffffu, sum, off);
        float omx  = __shfl_down_sync(0xffffffffu, mx,  off);
        int   omi  = __shfl_down_sync(0xffffffffu, mi,  off);
        sum += osum;
        if (omx > mx || (omx == mx && omi < mi)) { mx = omx; mi = omi; }
    }

    __shared__ float ssum[8];
    __shared__ float smx[8];
    __shared__ int   smi[8];
    const int w = t >> 5, l = t & 31;
    if (l == 0) { ssum[w] = sum; smx[w] = mx; smi[w] = mi; }
    __syncthreads();

    if (t == 0) {
        #pragma unroll
        for (int w2 = 1; w2 < 8; w2++) {
            sum += ssum[w2];
            if (smx[w2] > mx || (smx[w2] == mx && smi[w2] < mi)) {
                mx = smx[w2]; mi = smi[w2];
            }
        }

        // ---- label-loss term for this (b,s,k) ----
        const float* __restrict__ lp =
            cp + ((size_t)(bs * 22 + NK + k) << 14);     // lb map, first 9 used
        const float* __restrict__ lb = lab + (size_t)(b * NK + k) * 11;

        const float gx = lb[9];
        const float gy = lb[10];
        const bool valid = (gx > 0.0f) && (gy > 0.0f) &&
                           (gx < 128.0f) && (gy < 128.0f);

        const float xf = (float)(mi >> 7);    // index // 128
        const float yf = (float)(mi & 127);   // index % 128

        const float dx = gx + lb[7] - xf - lp[7];
        const float dy = gy + lb[8] - yf - lp[8];
        const float xy_loss = dx * dx + dy * dy;

        const float c = 1.0f - mx;
        const float conf_loss = c * c;

        float cls = 0.0f;
        #pragma unroll
        for (int j = 0; j < 7; j++) {
            const float d = lp[j] - lb[j];
            cls = fmaf(d, d, cls);
        }

        // L1-bypass stores: land in L2, visible to any finisher on any SM.
        __stcg(&g_part[bsk], sum);
        __stcg(&g_part[NBSK + bsk],
               valid ? (cls + xy_loss + conf_loss) : 0.0f);

        // Release-only ordering; reader side uses ld.cg (L1-bypass), so no
        // acquire (and no L1 invalidate) is needed anywhere.
        const unsigned prev = atom_add_release_gpu(&g_cnt[bs], 1u);
        if (prev == NK - 1) {
            g_cnt[bs] = 0;               // reset for next graph replay
            float hsum = 0.0f, lsum = 0.0f;
            #pragma unroll
            for (int kk = 0; kk < NK; kk++) {
                hsum += __ldcg(&g_part[bs * NK + kk]);
                lsum += __ldcg(&g_part[NBSK + bs * NK + kk]);
            }
            out[bs]      = hsum;         // heat_loss (16,4)
            out[64 + bs] = lsum;         // label_loss (16,4)
        }
    }
}

extern "C" void kernel_launch(void* const* d_in, const int* in_sizes, int n_in,
                              void* d_out, int out_size)
{
    const float* cp   = (const float*)d_in[0]; // combined_preds
    const float* heat = (const float*)d_in[1]; // heatmaps
    const float* lab  = (const float*)d_in[2]; // labels
    float* out = (float*)d_out;

    keypoint_main_kernel<<<NBSK, 256>>>(cp, heat, lab, out);
}

// round 8
// speedup vs baseline: 2.1637x; 1.1905x over previous
#include <cuda_runtime.h>

#define NB 16
#define NS 4
#define NK 11
#define NBS (NB * NS)         // 64
#define NBSK (NB * NS * NK)   // 704
#define NTHR 128

// Scratch: per-(b,s,k) partials + per-(b,s) arrival counters. Static device
// globals (no allocation). Counters zero at load; finisher resets them each
// launch so graph replays stay deterministic.
__device__ float    g_part[2 * NBSK];
__device__ unsigned g_cnt[NBS];

// RELEASE-only atomic: orders prior .cg stores; no acquire half -> no
// CCTL.IVALL (L1 invalidate). Reader uses ld.cg so no acquire needed.
__device__ __forceinline__ unsigned atom_add_release_gpu(unsigned* p, unsigned v)
{
    unsigned old;
    asm volatile("atom.release.gpu.global.add.u32 %0, [%1], %2;"
                 : "=r"(old) : "l"(p), "r"(v) : "memory");
    return old;
}

// 128 threads, force >=5 CTAs/SM resident so all 704 CTAs fit in ONE wave
// (148*5 = 740 slots). No wave-quantization tail; DRAM stream never drains.
__global__ void __launch_bounds__(NTHR, 5)
keypoint_main_kernel(const float* __restrict__ cp,     // (16,4,22,128,128)
                     const float* __restrict__ heat,   // (16,11,128,128)
                     const float* __restrict__ lab,    // (16,11,11)
                     float* __restrict__ out)          // 128 floats
{
    const int bsk = blockIdx.x;          // 0..703
    const int k   = bsk % NK;
    const int bs  = bsk / NK;            // b*4+s
    const int b   = bs >> 2;

    const float4* __restrict__ hptr =
        (const float4*)(cp + ((size_t)(bs * 22 + k) << 14));
    const float4* __restrict__ gptr =
        (const float4*)(heat + ((size_t)(b * NK + k) << 14));

    const int t = threadIdx.x;           // 0..127

    // Two independent FMA accumulators to shorten dependency chains.
    float s0 = 0.0f, s1 = 0.0f;
    float mx = -__int_as_float(0x7f800000); // -inf
    int   mi = 0;

    // 4096 float4 per map / 128 threads = 32 f4 per thread (h) + 32 (g).
    // Process in batches of 4 so ptxas keeps 8 float4 loads in flight.
    #pragma unroll
    for (int j = 0; j < 8; j++) {
        float4 h[4], g[4];
        #pragma unroll
        for (int u = 0; u < 4; u++) {
            const int v = t + (j * 4 + u) * NTHR;   // [0,4096)
            h[u] = hptr[v];
            g[u] = gptr[v];
        }
        #pragma unroll
        for (int u = 0; u < 4; u++) {
            const int v = t + (j * 4 + u) * NTHR;
            float d0 = h[u].x - g[u].x, d1 = h[u].y - g[u].y;
            float d2 = h[u].z - g[u].z, d3 = h[u].w - g[u].w;
            s0 = fmaf(d0, d0, s0);
            s1 = fmaf(d1, d1, s1);
            s0 = fmaf(d2, d2, s0);
            s1 = fmaf(d3, d3, s1);
            const int base = v << 2;
            // ascending index within thread -> strict > = first occurrence
            if (h[u].x > mx) { mx = h[u].x; mi = base; }
            if (h[u].y > mx) { mx = h[u].y; mi = base + 1; }
            if (h[u].z > mx) { mx = h[u].z; mi = base + 2; }
            if (h[u].w > mx) { mx = h[u].w; mi = base + 3; }
        }
    }
    float sum = s0 + s1;

    // Warp reduce (sum, argmax with lowest-index tiebreak)
    #pragma unroll
    for (int off = 16; off > 0; off >>= 1) {
        float osum = __shfl_down_sync(0xffffffffu, sum, off);
        float omx  = __shfl_down_sync(0xffffffffu, mx,  off);
        int   omi  = __shfl_down_sync(0xffffffffu, mi,  off);
        sum += osum;
        if (omx > mx || (omx == mx && omi < mi)) { mx = omx; mi = omi; }
    }

    __shared__ float ssum[4];
    __shared__ float smx[4];
    __shared__ int   smi[4];
    const int w = t >> 5, l = t & 31;
    if (l == 0) { ssum[w] = sum; smx[w] = mx; smi[w] = mi; }
    __syncthreads();

    if (t == 0) {
        #pragma unroll
        for (int w2 = 1; w2 < 4; w2++) {
            sum += ssum[w2];
            if (smx[w2] > mx || (smx[w2] == mx && smi[w2] < mi)) {
                mx = smx[w2]; mi = smi[w2];
            }
        }

        // ---- label-loss term for this (b,s,k) ----
        const float* __restrict__ lp =
            cp + ((size_t)(bs * 22 + NK + k) << 14);     // lb map, first 9 used
        const float* __restrict__ lb = lab + (size_t)(b * NK + k) * 11;

        const float gx = lb[9];
        const float gy = lb[10];
        const bool valid = (gx > 0.0f) && (gy > 0.0f) &&
                           (gx < 128.0f) && (gy < 128.0f);

        const float xf = (float)(mi >> 7);    // index // 128
        const float yf = (float)(mi & 127);   // index % 128

        const float dx = gx + lb[7] - xf - lp[7];
        const float dy = gy + lb[8] - yf - lp[8];
        const float xy_loss = dx * dx + dy * dy;

        const float c = 1.0f - mx;
        const float conf_loss = c * c;

        float cls = 0.0f;
        #pragma unroll
        for (int j = 0; j < 7; j++) {
            const float d = lp[j] - lb[j];
            cls = fmaf(d, d, cls);
        }

        // L1-bypass stores: land in L2, visible to any finisher on any SM.
        __stcg(&g_part[bsk], sum);
        __stcg(&g_part[NBSK + bsk],
               valid ? (cls + xy_loss + conf_loss) : 0.0f);

        // Release-only ordering; reader uses ld.cg (L1-bypass).
        const unsigned prev = atom_add_release_gpu(&g_cnt[bs], 1u);
        if (prev == NK - 1) {
            g_cnt[bs] = 0;               // reset for next graph replay
            float hsum = 0.0f, lsum = 0.0f;
            #pragma unroll
            for (int kk = 0; kk < NK; kk++) {
                hsum += __ldcg(&g_part[bs * NK + kk]);
                lsum += __ldcg(&g_part[NBSK + bs * NK + kk]);
            }
            out[bs]      = hsum;         // heat_loss (16,4)
            out[64 + bs] = lsum;         // label_loss (16,4)
        }
    }
}

extern "C" void kernel_launch(void* const* d_in, const int* in_sizes, int n_in,
                              void* d_out, int out_size)
{
    const float* cp   = (const float*)d_in[0]; // combined_preds
    const float* heat = (const float*)d_in[1]; // heatmaps
    const float* lab  = (const float*)d_in[2]; // labels
    float* out = (float*)d_out;

    keypoint_main_kernel<<<NBSK, NTHR>>>(cp, heat, lab, out);
}

// round 9
// speedup vs baseline: 2.1701x; 1.0030x over previous
#include <cuda_runtime.h>

#define NB 16
#define NS 4
#define NK 11
#define NBS (NB * NS)         // 64
#define NBSK (NB * NS * NK)   // 704
#define NTHR 128

// Scratch: per-(b,s,k) partials + per-(b,s) arrival counters. Static device
// globals (no allocation). Counters zero at load; finisher resets them each
// launch so graph replays stay deterministic.
__device__ float    g_part[2 * NBSK];
__device__ unsigned g_cnt[NBS];

// RELEASE-only atomic: orders prior .cg stores; no acquire half -> no
// CCTL.IVALL (L1 invalidate). Reader uses ld.cg so no acquire needed.
__device__ __forceinline__ unsigned atom_add_release_gpu(unsigned* p, unsigned v)
{
    unsigned old;
    asm volatile("atom.release.gpu.global.add.u32 %0, [%1], %2;"
                 : "=r"(old) : "l"(p), "r"(v) : "memory");
    return old;
}

// 128 threads, >=5 CTAs/SM resident: all 704 CTAs in ONE wave (148*5=740).
__global__ void __launch_bounds__(NTHR, 5)
keypoint_main_kernel(const float* __restrict__ cp,     // (16,4,22,128,128)
                     const float* __restrict__ heat,   // (16,11,128,128)
                     const float* __restrict__ lab,    // (16,11,11)
                     float* __restrict__ out)          // 128 floats
{
    const int bsk = blockIdx.x;          // 0..703
    const int k   = bsk % NK;
    const int bs  = bsk / NK;            // b*4+s
    const int b   = bs >> 2;

    const float4* __restrict__ hptr =
        (const float4*)(cp + ((size_t)(bs * 22 + k) << 14));
    const float4* __restrict__ gptr =
        (const float4*)(heat + ((size_t)(b * NK + k) << 14));

    const int t = threadIdx.x;           // 0..127

    float s0 = 0.0f, s1 = 0.0f, s2 = 0.0f, s3 = 0.0f;
    float mx = -__int_as_float(0x7f800000); // -inf
    int   mi = 0;

    // 4096 float4/map / 128 thr = 32 f4 per thread per stream.
    // Software-pipelined ping-pong: prefetch batch j+1 (8 LDG.128) BEFORE
    // computing batch j, so ~8 loads stay continuously in flight per thread.
    float4 ha[4], ga[4], hb[4], gb[4];

    #pragma unroll
    for (int u = 0; u < 4; u++) {
        ha[u] = hptr[t + u * NTHR];
        ga[u] = gptr[t + u * NTHR];
    }

    #pragma unroll
    for (int j = 0; j < 8; j++) {
        const bool cur_a = ((j & 1) == 0);   // compile-time after unroll

        // prefetch next batch into the other buffer
        if (j < 7) {
            #pragma unroll
            for (int u = 0; u < 4; u++) {
                const int v = t + ((j + 1) * 4 + u) * NTHR;
                if (cur_a) { hb[u] = hptr[v]; gb[u] = gptr[v]; }
                else       { ha[u] = hptr[v]; ga[u] = gptr[v]; }
            }
        }

        // consume current batch
        #pragma unroll
        for (int u = 0; u < 4; u++) {
            const float4 h = cur_a ? ha[u] : hb[u];
            const float4 g = cur_a ? ga[u] : gb[u];
            const int v = t + (j * 4 + u) * NTHR;
            float d0 = h.x - g.x, d1 = h.y - g.y;
            float d2 = h.z - g.z, d3 = h.w - g.w;
            s0 = fmaf(d0, d0, s0);
            s1 = fmaf(d1, d1, s1);
            s2 = fmaf(d2, d2, s2);
            s3 = fmaf(d3, d3, s3);
            const int base = v << 2;
            // ascending index within thread -> strict > = first occurrence
            if (h.x > mx) { mx = h.x; mi = base; }
            if (h.y > mx) { mx = h.y; mi = base + 1; }
            if (h.z > mx) { mx = h.z; mi = base + 2; }
            if (h.w > mx) { mx = h.w; mi = base + 3; }
        }
    }
    float sum = (s0 + s1) + (s2 + s3);

    // Warp reduce (sum, argmax with lowest-index tiebreak)
    #pragma unroll
    for (int off = 16; off > 0; off >>= 1) {
        float osum = __shfl_down_sync(0xffffffffu, sum, off);
        float omx  = __shfl_down_sync(0xffffffffu, mx,  off);
        int   omi  = __shfl_down_sync(0xffffffffu, mi,  off);
        sum += osum;
        if (omx > mx || (omx == mx && omi < mi)) { mx = omx; mi = omi; }
    }

    __shared__ float ssum[4];
    __shared__ float smx[4];
    __shared__ int   smi[4];
    const int w = t >> 5, l = t & 31;
    if (l == 0) { ssum[w] = sum; smx[w] = mx; smi[w] = mi; }
    __syncthreads();

    if (t == 0) {
        #pragma unroll
        for (int w2 = 1; w2 < 4; w2++) {
            sum += ssum[w2];
            if (smx[w2] > mx || (smx[w2] == mx && smi[w2] < mi)) {
                mx = smx[w2]; mi = smi[w2];
            }
        }

        // ---- label-loss term for this (b,s,k) ----
        const float* __restrict__ lp =
            cp + ((size_t)(bs * 22 + NK + k) << 14);     // lb map, first 9 used
        const float* __restrict__ lb = lab + (size_t)(b * NK + k) * 11;

        const float gx = lb[9];
        const float gy = lb[10];
        const bool valid = (gx > 0.0f) && (gy > 0.0f) &&
                           (gx < 128.0f) && (gy < 128.0f);

        const float xf = (float)(mi >> 7);    // index // 128
        const float yf = (float)(mi & 127);   // index % 128

        const float dx = gx + lb[7] - xf - lp[7];
        const float dy = gy + lb[8] - yf - lp[8];
        const float xy_loss = dx * dx + dy * dy;

        const float c = 1.0f - mx;
        const float conf_loss = c * c;

        float cls = 0.0f;
        #pragma unroll
        for (int j = 0; j < 7; j++) {
            const float d = lp[j] - lb[j];
            cls = fmaf(d, d, cls);
        }

        // L1-bypass stores: land in L2, visible to any finisher on any SM.
        __stcg(&g_part[bsk], sum);
        __stcg(&g_part[NBSK + bsk],
               valid ? (cls + xy_loss + conf_loss) : 0.0f);

        // Release-only ordering; reader uses ld.cg (L1-bypass).
        const unsigned prev = atom_add_release_gpu(&g_cnt[bs], 1u);
        if (prev == NK - 1) {
            g_cnt[bs] = 0;               // reset for next graph replay
            float hsum = 0.0f, lsum = 0.0f;
            #pragma unroll
            for (int kk = 0; kk < NK; kk++) {
                hsum += __ldcg(&g_part[bs * NK + kk]);
                lsum += __ldcg(&g_part[NBSK + bs * NK + kk]);
            }
            out[bs]      = hsum;         // heat_loss (16,4)
            out[64 + bs] = lsum;         // label_loss (16,4)
        }
    }
}

extern "C" void kernel_launch(void* const* d_in, const int* in_sizes, int n_in,
                              void* d_out, int out_size)
{
    const float* cp   = (const float*)d_in[0]; // combined_preds
    const float* heat = (const float*)d_in[1]; // heatmaps
    const float* lab  = (const float*)d_in[2]; // labels
    float* out = (float*)d_out;

    keypoint_main_kernel<<<NBSK, NTHR>>>(cp, heat, lab, out);
}